// round 3
// baseline (speedup 1.0000x reference)
#include <cuda_runtime.h>

#define B_      2048
#define D_      512
#define NA_     512
#define CAP_    32
#define NVMAX_  8       // vectors per matrix pass
#define NSL_    4       // row slices per matrix
#define RPC_    128     // rows per CTA
#define RPW_    16      // rows per warp (8 warps)

// ---------------- device scratch ----------------
__device__ int g_counts[NA_];
__device__ int g_buckets[NA_ * CAP_];
__device__ int g_ovf_count;
__device__ int g_ovf[B_];

// ---------------- kernel 0: reset ----------------
__global__ void k_zero() {
    int t = threadIdx.x;
    if (t < NA_) g_counts[t] = 0;
    if (t == 0)  g_ovf_count = 0;
}

// ---------------- kernel 1: bucket by attribute ----------------
__global__ void k_bucket(const int* __restrict__ attrs) {
    int b = blockIdx.x * blockDim.x + threadIdx.x;
    if (b >= B_) return;
    int a = attrs[b];
    int pos = atomicAdd(&g_counts[a], 1);
    if (pos < CAP_) {
        g_buckets[a * CAP_ + pos] = b;
    } else {
        int o = atomicAdd(&g_ovf_count, 1);
        g_ovf[o] = b;
    }
}

// ---------------- warp-per-row, 4-row batched, multi-vector dot ----------
// Per batch: issue 16 LDG.128 (2KB in flight), then for each sample j:
// 4 LDS.128 (vector reused across the 4 rows), 64 FFMA, 4x5 shfl reduce.
template <int NV>
__device__ __forceinline__ void compute_slice(
    const float* __restrict__ M,
    const float4* __restrict__ sv4,    // smem vectors [NV][128] float4
    float* __restrict__ sout,          // smem out stage [NV][RPC_]
    int nv, int row0, int warp, int lane)
{
#pragma unroll
    for (int rb = 0; rb < RPW_ / 4; rb++) {
        int lrow0 = warp * RPW_ + rb * 4;

        float4 m[4][4];
#pragma unroll
        for (int r = 0; r < 4; r++) {
            const float4* mrow =
                (const float4*)(M + (size_t)(row0 + lrow0 + r) * D_);
#pragma unroll
            for (int s = 0; s < 4; s++) m[r][s] = mrow[s * 32 + lane];
        }

#pragma unroll
        for (int j = 0; j < NV; j++) {
            float4 v0 = sv4[j * 128 + lane];
            float4 v1 = sv4[j * 128 + 32 + lane];
            float4 v2 = sv4[j * 128 + 64 + lane];
            float4 v3 = sv4[j * 128 + 96 + lane];
#pragma unroll
            for (int r = 0; r < 4; r++) {
                float x;
                x = m[r][0].x * v0.x;
                x = fmaf(m[r][0].y, v0.y, x);
                x = fmaf(m[r][0].z, v0.z, x);
                x = fmaf(m[r][0].w, v0.w, x);
                x = fmaf(m[r][1].x, v1.x, x);
                x = fmaf(m[r][1].y, v1.y, x);
                x = fmaf(m[r][1].z, v1.z, x);
                x = fmaf(m[r][1].w, v1.w, x);
                x = fmaf(m[r][2].x, v2.x, x);
                x = fmaf(m[r][2].y, v2.y, x);
                x = fmaf(m[r][2].z, v2.z, x);
                x = fmaf(m[r][2].w, v2.w, x);
                x = fmaf(m[r][3].x, v3.x, x);
                x = fmaf(m[r][3].y, v3.y, x);
                x = fmaf(m[r][3].z, v3.z, x);
                x = fmaf(m[r][3].w, v3.w, x);
                x += __shfl_xor_sync(0xffffffffu, x, 16);
                x += __shfl_xor_sync(0xffffffffu, x, 8);
                x += __shfl_xor_sync(0xffffffffu, x, 4);
                x += __shfl_xor_sync(0xffffffffu, x, 2);
                x += __shfl_xor_sync(0xffffffffu, x, 1);
                if (j < nv && lane == j)
                    sout[j * RPC_ + lrow0 + r] = (x > 0.0f) ? x : 0.0f;
            }
        }
    }
}

// ---------------- kernel 2: per-attribute multi-vector matvec ----------
// grid = (NA_, NSL_): x = attribute, y = 128-row slice. 256 threads.
// Also handles overflow samples at the end (grid-strided), so no 4th kernel.
__global__ __launch_bounds__(256, 2) void k_compute(
    const int*   __restrict__ attrs,
    const int*   __restrict__ objs,
    const float* __restrict__ attr_ops,
    const float* __restrict__ obj_emb,
    float*       __restrict__ out)
{
    __shared__ float sv[NVMAX_ * D_];      // 16 KB
    __shared__ float sout[NVMAX_ * RPC_];  // 4 KB
    __shared__ int   ssamp[NVMAX_];

    int tid  = threadIdx.x;
    int lane = tid & 31;
    int warp = tid >> 5;
    int a    = blockIdx.x;
    int row0 = blockIdx.y * RPC_;

    int cnt = g_counts[a];
    if (cnt > CAP_) cnt = CAP_;

    if (cnt > 0) {
        const float* M = attr_ops + (size_t)a * D_ * D_;

        for (int base = 0; base < cnt; base += NVMAX_) {
            int nv = cnt - base;
            if (nv > NVMAX_) nv = NVMAX_;
            int NVsel = (nv <= 1) ? 1 : (nv <= 2) ? 2 : (nv <= 4) ? 4 : 8;

            __syncthreads();   // protect sv/sout reuse across passes
            if (tid < nv) ssamp[tid] = g_buckets[a * CAP_ + base + tid];
            __syncthreads();

            // cooperative vector load: 2 vectors per 256-thread pass
            for (int j = tid >> 7; j < nv; j += 2) {
                int o = objs[ssamp[j]];
                ((float4*)sv)[j * 128 + (tid & 127)] =
                    ((const float4*)(obj_emb + (size_t)o * D_))[tid & 127];
            }
            __syncthreads();

            switch (NVsel) {
                case 1: compute_slice<1>(M, (const float4*)sv, sout, nv, row0, warp, lane); break;
                case 2: compute_slice<2>(M, (const float4*)sv, sout, nv, row0, warp, lane); break;
                case 4: compute_slice<4>(M, (const float4*)sv, sout, nv, row0, warp, lane); break;
                default: compute_slice<8>(M, (const float4*)sv, sout, nv, row0, warp, lane); break;
            }
            __syncthreads();

            // coalesced write-out: 128 contiguous floats per sample slice
            for (int idx = tid; idx < nv * RPC_; idx += 256) {
                int j  = idx >> 7;
                int rl = idx & 127;
                out[(size_t)ssamp[j] * D_ + row0 + rl] = sout[idx];
            }
        }
    }

    // ---- overflow samples (rare; correctness safety net) ----
    int novf = g_ovf_count;
    for (int i = blockIdx.x; i < novf; i += NA_) {
        int b = g_ovf[i];
        int o = objs[b];
        const float* M2 = attr_ops + (size_t)attrs[b] * D_ * D_;

        __syncthreads();
        for (int t = tid; t < 128; t += 256)
            ((float4*)sv)[t] = ((const float4*)(obj_emb + (size_t)o * D_))[t];
        __syncthreads();

        compute_slice<1>(M2, (const float4*)sv, sout, 1, row0, warp, lane);
        __syncthreads();

        for (int idx = tid; idx < RPC_; idx += 256)
            out[(size_t)b * D_ + row0 + idx] = sout[idx];
    }
}

// ---------------- launch -------------------------------------------------
extern "C" void kernel_launch(void* const* d_in, const int* in_sizes, int n_in,
                              void* d_out, int out_size)
{
    const int*   attrs    = (const int*)d_in[0];
    const int*   objs     = (const int*)d_in[1];
    const float* attr_ops = (const float*)d_in[2];
    const float* obj_emb  = (const float*)d_in[3];
    float*       out      = (float*)d_out;

    k_zero<<<1, 512>>>();
    k_bucket<<<(B_ + 255) / 256, 256>>>(attrs);
    k_compute<<<dim3(NA_, NSL_), 256>>>(attrs, objs, attr_ops, obj_emb, out);
}

// round 4
// speedup vs baseline: 1.5455x; 1.5455x over previous
#include <cuda_runtime.h>

#define B_      2048
#define D_      512
#define NA_     512
#define CAP_    32
#define NVMAX_  16      // vectors per matrix pass
#define NSL_    8       // row slices per matrix
#define RPC_    64      // rows per CTA
#define RPW_    8       // rows per warp (8 warps)

// ---------------- device scratch ----------------
__device__ int g_counts[NA_];
__device__ int g_buckets[NA_ * CAP_];
__device__ int g_ovf_count;
__device__ int g_ovf[B_];

// ---------------- kernel 0: reset ----------------
__global__ void k_zero() {
    int t = threadIdx.x;
    if (t < NA_) g_counts[t] = 0;
    if (t == 0)  g_ovf_count = 0;
}

// ---------------- kernel 1: bucket by attribute ----------------
__global__ void k_bucket(const int* __restrict__ attrs) {
    int b = blockIdx.x * blockDim.x + threadIdx.x;
    if (b >= B_) return;
    int a = attrs[b];
    int pos = atomicAdd(&g_counts[a], 1);
    if (pos < CAP_) {
        g_buckets[a * CAP_ + pos] = b;
    } else {
        int o = atomicAdd(&g_ovf_count, 1);
        g_ovf[o] = b;
    }
}

// ---------------- warp-per-row, 2-row batched, multi-vector dot ----------
// Per 2-row batch: 8 LDG.128 streaming (1KB in flight/warp), then per sample:
// 4 LDS.128 shared across both rows, 2x16 FFMA, 2x5 SHFL reduce.
template <int NV>
__device__ __forceinline__ void compute_slice(
    const float* __restrict__ M,
    const float4* __restrict__ sv4,    // smem vectors [NV][128] float4
    float* __restrict__ sout,          // smem out stage [NV][RPC_]
    int nv, int row0, int warp, int lane)
{
#pragma unroll
    for (int rb = 0; rb < RPW_ / 2; rb++) {
        int lrow0 = warp * RPW_ + rb * 2;

        float4 m[2][4];
#pragma unroll
        for (int r = 0; r < 2; r++) {
            const float4* mrow =
                (const float4*)(M + (size_t)(row0 + lrow0 + r) * D_);
#pragma unroll
            for (int s = 0; s < 4; s++) m[r][s] = __ldcs(&mrow[s * 32 + lane]);
        }

#pragma unroll
        for (int j = 0; j < NV; j++) {
            float4 v0 = sv4[j * 128 + lane];
            float4 v1 = sv4[j * 128 + 32 + lane];
            float4 v2 = sv4[j * 128 + 64 + lane];
            float4 v3 = sv4[j * 128 + 96 + lane];
#pragma unroll
            for (int r = 0; r < 2; r++) {
                float x;
                x = m[r][0].x * v0.x;
                x = fmaf(m[r][0].y, v0.y, x);
                x = fmaf(m[r][0].z, v0.z, x);
                x = fmaf(m[r][0].w, v0.w, x);
                x = fmaf(m[r][1].x, v1.x, x);
                x = fmaf(m[r][1].y, v1.y, x);
                x = fmaf(m[r][1].z, v1.z, x);
                x = fmaf(m[r][1].w, v1.w, x);
                x = fmaf(m[r][2].x, v2.x, x);
                x = fmaf(m[r][2].y, v2.y, x);
                x = fmaf(m[r][2].z, v2.z, x);
                x = fmaf(m[r][2].w, v2.w, x);
                x = fmaf(m[r][3].x, v3.x, x);
                x = fmaf(m[r][3].y, v3.y, x);
                x = fmaf(m[r][3].z, v3.z, x);
                x = fmaf(m[r][3].w, v3.w, x);
                x += __shfl_xor_sync(0xffffffffu, x, 16);
                x += __shfl_xor_sync(0xffffffffu, x, 8);
                x += __shfl_xor_sync(0xffffffffu, x, 4);
                x += __shfl_xor_sync(0xffffffffu, x, 2);
                x += __shfl_xor_sync(0xffffffffu, x, 1);
                if (j < nv && lane == j)
                    sout[j * RPC_ + lrow0 + r] = (x > 0.0f) ? x : 0.0f;
            }
        }
    }
}

// ---------------- kernel 2: per-attribute multi-vector matvec ----------
// grid = (NA_, NSL_): x = attribute, y = 64-row slice. 256 threads.
__global__ __launch_bounds__(256) void k_compute(
    const int*   __restrict__ objs,
    const float* __restrict__ attr_ops,
    const float* __restrict__ obj_emb,
    float*       __restrict__ out)
{
    __shared__ float sv[NVMAX_ * D_];      // 32 KB
    __shared__ float sout[NVMAX_ * RPC_];  // 4 KB
    __shared__ int   ssamp[NVMAX_];

    int a = blockIdx.x;
    int cnt = g_counts[a];
    if (cnt > CAP_) cnt = CAP_;
    if (cnt == 0) return;

    int tid  = threadIdx.x;
    int lane = tid & 31;
    int warp = tid >> 5;
    int row0 = blockIdx.y * RPC_;
    const float* M = attr_ops + (size_t)a * D_ * D_;

    for (int base = 0; base < cnt; base += NVMAX_) {
        int nv = cnt - base;
        if (nv > NVMAX_) nv = NVMAX_;
        int NVsel = (nv <= 1) ? 1 : (nv <= 2) ? 2 : (nv <= 4) ? 4 : (nv <= 8) ? 8 : 16;

        __syncthreads();   // smem reuse guard across passes
        if (tid < nv) ssamp[tid] = g_buckets[a * CAP_ + base + tid];
        __syncthreads();

        // cooperative vector load: 2 vectors per 256-thread pass
        for (int j = tid >> 7; j < nv; j += 2) {
            int o = objs[ssamp[j]];
            ((float4*)sv)[j * 128 + (tid & 127)] =
                ((const float4*)(obj_emb + (size_t)o * D_))[tid & 127];
        }
        __syncthreads();

        switch (NVsel) {
            case 1:  compute_slice<1> (M, (const float4*)sv, sout, nv, row0, warp, lane); break;
            case 2:  compute_slice<2> (M, (const float4*)sv, sout, nv, row0, warp, lane); break;
            case 4:  compute_slice<4> (M, (const float4*)sv, sout, nv, row0, warp, lane); break;
            case 8:  compute_slice<8> (M, (const float4*)sv, sout, nv, row0, warp, lane); break;
            default: compute_slice<16>(M, (const float4*)sv, sout, nv, row0, warp, lane); break;
        }
        __syncthreads();

        // coalesced write-out: 64 contiguous floats per sample slice
        for (int idx = tid; idx < nv * RPC_; idx += 256) {
            int j  = idx >> 6;
            int rl = idx & 63;
            out[(size_t)ssamp[j] * D_ + row0 + rl] = sout[idx];
        }
    }
}

// ---------------- kernel 3: overflow fallback (grid-stride) ------------
__global__ __launch_bounds__(256) void k_ovf(
    const int*   __restrict__ attrs,
    const int*   __restrict__ objs,
    const float* __restrict__ attr_ops,
    const float* __restrict__ obj_emb,
    float*       __restrict__ out)
{
    __shared__ float sv[D_];
    int n = g_ovf_count;
    for (int i = blockIdx.x; i < n; i += gridDim.x) {
        int b = g_ovf[i];
        int a = attrs[b];
        int o = objs[b];
        int tid = threadIdx.x;

        __syncthreads();
        sv[tid]       = obj_emb[(size_t)o * D_ + tid];
        sv[tid + 256] = obj_emb[(size_t)o * D_ + tid + 256];
        __syncthreads();

        const float* M = attr_ops + (size_t)a * D_ * D_;
#pragma unroll
        for (int rr = 0; rr < 2; rr++) {
            int row = tid + rr * 256;
            const float4* mr = (const float4*)(M + (size_t)row * D_);
            float acc = 0.0f;
#pragma unroll 4
            for (int k = 0; k < D_ / 4; k++) {
                float4 m = mr[k];
                float4 v = ((const float4*)sv)[k];
                acc += m.x * v.x + m.y * v.y + m.z * v.z + m.w * v.w;
            }
            out[(size_t)b * D_ + row] = (acc > 0.0f) ? acc : 0.0f;
        }
    }
}

// ---------------- launch -------------------------------------------------
extern "C" void kernel_launch(void* const* d_in, const int* in_sizes, int n_in,
                              void* d_out, int out_size)
{
    const int*   attrs    = (const int*)d_in[0];
    const int*   objs     = (const int*)d_in[1];
    const float* attr_ops = (const float*)d_in[2];
    const float* obj_emb  = (const float*)d_in[3];
    float*       out      = (float*)d_out;

    k_zero<<<1, 512>>>();
    k_bucket<<<(B_ + 255) / 256, 256>>>(attrs);
    k_compute<<<dim3(NA_, NSL_), 256>>>(objs, attr_ops, obj_emb, out);
    k_ovf<<<64, 256>>>(attrs, objs, attr_ops, obj_emb, out);
}